// round 1
// baseline (speedup 1.0000x reference)
#include <cuda_runtime.h>
#include <math.h>

// ---------------------------------------------------------------------------
// Problem constants
// ---------------------------------------------------------------------------
#define NMAX 500000
#define CCH  64
#define KTAP 27

static const int NCL_H[3] = {4096, 32768, 131072};

// ---------------------------------------------------------------------------
// Device scratch (module-scope; no runtime allocation)
// ---------------------------------------------------------------------------
__device__ float  g_bufX[NMAX * CCH];      // GEMM/conv output scratch
__device__ float  g_bufP[NMAX * CCH];      // pw / f_last scratch
__device__ float  g_bufF[NMAX * CCH];      // fused (residual)
__device__ float  g_cA[131072 * CCH];      // cluster sums / pfeat sums
__device__ float  g_cB[131072 * CCH];      // cluster softmax denominators
__device__ float  g_ccnt[131072];          // cluster counts
__device__ float  g_adp[NMAX * 3];         // adaptive weights
__device__ double g_stats[2 * CCH];        // BN: per-channel sum, sumsq
__device__ float  g_gmax;                  // global max for exp-normalize

// ---------------------------------------------------------------------------
// Helpers
// ---------------------------------------------------------------------------
__device__ __forceinline__ void atomicMaxFloat(float* addr, float val) {
    int old = __float_as_int(*addr);
    while (__int_as_float(old) < val) {
        int assumed = old;
        old = atomicCAS((int*)addr, assumed, __float_as_int(val));
        if (old == assumed) break;
    }
}

// BN coefficients from accumulated stats (train-mode batch stats, eps=1e-3)
__device__ __forceinline__ float bn_apply(float x, int c, float invN,
                                          const float* __restrict__ gamma,
                                          const float* __restrict__ beta) {
    float mu  = (float)g_stats[c] * invN;
    float ex2 = (float)g_stats[CCH + c] * invN;
    float var = ex2 - mu * mu;
    float rs  = rsqrtf(var + 1e-3f);
    return (x - mu) * rs * gamma[c] + beta[c];
}

// ---------------------------------------------------------------------------
// Shared-memory layout for tiled GEMM/conv  (dynamic smem)
//   XS : transposed input tile  [64][132]  (X^T: XS[c*132 + row])
//   WS : weight tile            [64][64]
//   SSUM/SSQ : per-channel partial stats [64] each
// ---------------------------------------------------------------------------
#define SM_XS (64 * 132)
#define SM_WS (64 * 64)
#define SMEM_FLOATS (SM_XS + SM_WS + 128)
#define SMEM_BYTES  (SMEM_FLOATS * 4)

// ---------------------------------------------------------------------------
// Tiled 64-wide GEMM:  Y[n][j] = sum_c Xin[n][c] * W[c][j]
//   MODE 0: Xin = X
//   MODE 1: Xin = X - csum[cl[n]]/max(ccnt[cl[n]],1)   (cluster mean subtract)
//   MODE 2: Y = X @ W[0:64] + X2 @ W[64:128]           (concat GEMM)
//   STATS  : accumulate per-channel sum/sumsq of Y into g_stats
//   MAXRED : accumulate global max of Y into g_gmax
// Tile: 128 rows x 64 cols, 128 threads, 8x8 outputs per thread.
// ---------------------------------------------------------------------------
template <int MODE, int STATS, int MAXRED>
__global__ void __launch_bounds__(128) gemm64(
    const float* __restrict__ X, const float* __restrict__ X2,
    const float* __restrict__ W, float* __restrict__ Y,
    const int* __restrict__ cl, const float* __restrict__ csum,
    const float* __restrict__ ccnt, int nrows)
{
    extern __shared__ float sm[];
    float* XS   = sm;
    float* WS   = sm + SM_XS;
    float* SSUM = WS + SM_WS;
    float* SSQ  = SSUM + 64;

    const int tid  = threadIdx.x;
    const int base = blockIdx.x * 128;

    if (STATS && tid < 64) { SSUM[tid] = 0.f; SSQ[tid] = 0.f; }

    float acc[8][8];
#pragma unroll
    for (int i = 0; i < 8; i++)
#pragma unroll
        for (int j = 0; j < 8; j++) acc[i][j] = 0.f;

    const int rbase = (tid >> 3) * 8;
    const int cbase = (tid & 7) * 8;
    const int NP = (MODE == 2) ? 2 : 1;

    for (int p = 0; p < NP; p++) {
        __syncthreads();
        // load weight tile
        const float4* Wp = (const float4*)(W + p * 4096);
        float4* WS4 = (float4*)WS;
#pragma unroll
        for (int i = 0; i < 8; i++) WS4[tid + i * 128] = Wp[tid + i * 128];

        // load X tile (one row per thread), store transposed
        const float* Xp = (MODE == 2 && p == 1) ? X2 : X;
        int n = base + tid;
        if (n < nrows) {
            const float4* src = (const float4*)(Xp + (size_t)n * 64);
            float minv = 0.f;
            const float4* mp = nullptr;
            if (MODE == 1) {
                int c0 = cl[n];
                float cnt = fmaxf(ccnt[c0], 1.f);
                minv = 1.f / cnt;
                mp = (const float4*)(csum + (size_t)c0 * 64);
            }
#pragma unroll
            for (int c4 = 0; c4 < 16; c4++) {
                float4 v = src[c4];
                if (MODE == 1) {
                    float4 m = mp[c4];
                    v.x -= m.x * minv; v.y -= m.y * minv;
                    v.z -= m.z * minv; v.w -= m.w * minv;
                }
                XS[(c4 * 4 + 0) * 132 + tid] = v.x;
                XS[(c4 * 4 + 1) * 132 + tid] = v.y;
                XS[(c4 * 4 + 2) * 132 + tid] = v.z;
                XS[(c4 * 4 + 3) * 132 + tid] = v.w;
            }
        } else {
#pragma unroll
            for (int c4 = 0; c4 < 16; c4++) {
                XS[(c4 * 4 + 0) * 132 + tid] = 0.f;
                XS[(c4 * 4 + 1) * 132 + tid] = 0.f;
                XS[(c4 * 4 + 2) * 132 + tid] = 0.f;
                XS[(c4 * 4 + 3) * 132 + tid] = 0.f;
            }
        }
        __syncthreads();

#pragma unroll 8
        for (int c = 0; c < 64; c++) {
            float4 a0 = *(const float4*)&XS[c * 132 + rbase];
            float4 a1 = *(const float4*)&XS[c * 132 + rbase + 4];
            float4 b0 = *(const float4*)&WS[c * 64 + cbase];
            float4 b1 = *(const float4*)&WS[c * 64 + cbase + 4];
            float av[8] = {a0.x, a0.y, a0.z, a0.w, a1.x, a1.y, a1.z, a1.w};
            float bv[8] = {b0.x, b0.y, b0.z, b0.w, b1.x, b1.y, b1.z, b1.w};
#pragma unroll
            for (int i = 0; i < 8; i++)
#pragma unroll
                for (int j = 0; j < 8; j++) acc[i][j] += av[i] * bv[j];
        }
    }

    // store
#pragma unroll
    for (int i = 0; i < 8; i++) {
        int n = base + rbase + i;
        if (n < nrows) {
            float4 o0 = make_float4(acc[i][0], acc[i][1], acc[i][2], acc[i][3]);
            float4 o1 = make_float4(acc[i][4], acc[i][5], acc[i][6], acc[i][7]);
            *(float4*)(Y + (size_t)n * 64 + cbase)     = o0;
            *(float4*)(Y + (size_t)n * 64 + cbase + 4) = o1;
        }
    }

    if (STATS) {
        float s[8] = {0, 0, 0, 0, 0, 0, 0, 0};
        float q[8] = {0, 0, 0, 0, 0, 0, 0, 0};
#pragma unroll
        for (int i = 0; i < 8; i++) {
            if (base + rbase + i < nrows) {
#pragma unroll
                for (int j = 0; j < 8; j++) {
                    s[j] += acc[i][j];
                    q[j] += acc[i][j] * acc[i][j];
                }
            }
        }
#pragma unroll
        for (int j = 0; j < 8; j++) {
            atomicAdd(&SSUM[cbase + j], s[j]);
            atomicAdd(&SSQ[cbase + j], q[j]);
        }
        __syncthreads();
        if (tid < 64) {
            atomicAdd(&g_stats[tid],      (double)SSUM[tid]);
            atomicAdd(&g_stats[64 + tid], (double)SSQ[tid]);
        }
    }

    if (MAXRED) {
        float m = -3.402823466e38f;
#pragma unroll
        for (int i = 0; i < 8; i++) {
            if (base + rbase + i < nrows) {
#pragma unroll
                for (int j = 0; j < 8; j++) m = fmaxf(m, acc[i][j]);
            }
        }
#pragma unroll
        for (int o = 16; o > 0; o >>= 1)
            m = fmaxf(m, __shfl_xor_sync(0xffffffffu, m, o));
        __shared__ float red[4];
        if ((tid & 31) == 0) red[tid >> 5] = m;
        __syncthreads();
        if (tid == 0) {
            m = fmaxf(fmaxf(red[0], red[1]), fmaxf(red[2], red[3]));
            atomicMaxFloat(&g_gmax, m);
        }
    }
}

// ---------------------------------------------------------------------------
// 27-tap submanifold conv:  Y[n][j] = sum_k sum_c F[nbr[n][k]][c] * Wc[k][c][j]
// Always accumulates BN stats of Y.
// ---------------------------------------------------------------------------
__global__ void __launch_bounds__(128) conv27(
    const float* __restrict__ F, const int* __restrict__ nbr,
    const float* __restrict__ Wc, float* __restrict__ Y, int nrows)
{
    extern __shared__ float sm[];
    float* XS   = sm;
    float* WS   = sm + SM_XS;
    float* SSUM = WS + SM_WS;
    float* SSQ  = SSUM + 64;

    const int tid  = threadIdx.x;
    const int base = blockIdx.x * 128;
    const int n    = base + tid;

    if (tid < 64) { SSUM[tid] = 0.f; SSQ[tid] = 0.f; }

    float acc[8][8];
#pragma unroll
    for (int i = 0; i < 8; i++)
#pragma unroll
        for (int j = 0; j < 8; j++) acc[i][j] = 0.f;

    const int rbase = (tid >> 3) * 8;
    const int cbase = (tid & 7) * 8;

    for (int k = 0; k < KTAP; k++) {
        __syncthreads();
        const float4* Wp = (const float4*)(Wc + k * 4096);
        float4* WS4 = (float4*)WS;
#pragma unroll
        for (int i = 0; i < 8; i++) WS4[tid + i * 128] = Wp[tid + i * 128];

        if (n < nrows) {
            int idx = nbr[n * KTAP + k];
            const float4* src = (const float4*)(F + (size_t)idx * 64);
#pragma unroll
            for (int c4 = 0; c4 < 16; c4++) {
                float4 v = src[c4];
                XS[(c4 * 4 + 0) * 132 + tid] = v.x;
                XS[(c4 * 4 + 1) * 132 + tid] = v.y;
                XS[(c4 * 4 + 2) * 132 + tid] = v.z;
                XS[(c4 * 4 + 3) * 132 + tid] = v.w;
            }
        } else {
#pragma unroll
            for (int c4 = 0; c4 < 16; c4++) {
                XS[(c4 * 4 + 0) * 132 + tid] = 0.f;
                XS[(c4 * 4 + 1) * 132 + tid] = 0.f;
                XS[(c4 * 4 + 2) * 132 + tid] = 0.f;
                XS[(c4 * 4 + 3) * 132 + tid] = 0.f;
            }
        }
        __syncthreads();

#pragma unroll 8
        for (int c = 0; c < 64; c++) {
            float4 a0 = *(const float4*)&XS[c * 132 + rbase];
            float4 a1 = *(const float4*)&XS[c * 132 + rbase + 4];
            float4 b0 = *(const float4*)&WS[c * 64 + cbase];
            float4 b1 = *(const float4*)&WS[c * 64 + cbase + 4];
            float av[8] = {a0.x, a0.y, a0.z, a0.w, a1.x, a1.y, a1.z, a1.w};
            float bv[8] = {b0.x, b0.y, b0.z, b0.w, b1.x, b1.y, b1.z, b1.w};
#pragma unroll
            for (int i = 0; i < 8; i++)
#pragma unroll
                for (int j = 0; j < 8; j++) acc[i][j] += av[i] * bv[j];
        }
    }

#pragma unroll
    for (int i = 0; i < 8; i++) {
        int nn = base + rbase + i;
        if (nn < nrows) {
            float4 o0 = make_float4(acc[i][0], acc[i][1], acc[i][2], acc[i][3]);
            float4 o1 = make_float4(acc[i][4], acc[i][5], acc[i][6], acc[i][7]);
            *(float4*)(Y + (size_t)nn * 64 + cbase)     = o0;
            *(float4*)(Y + (size_t)nn * 64 + cbase + 4) = o1;
        }
    }

    // stats
    {
        float s[8] = {0, 0, 0, 0, 0, 0, 0, 0};
        float q[8] = {0, 0, 0, 0, 0, 0, 0, 0};
#pragma unroll
        for (int i = 0; i < 8; i++) {
            if (base + rbase + i < nrows) {
#pragma unroll
                for (int j = 0; j < 8; j++) {
                    s[j] += acc[i][j];
                    q[j] += acc[i][j] * acc[i][j];
                }
            }
        }
#pragma unroll
        for (int j = 0; j < 8; j++) {
            atomicAdd(&SSUM[cbase + j], s[j]);
            atomicAdd(&SSQ[cbase + j], q[j]);
        }
        __syncthreads();
        if (tid < 64) {
            atomicAdd(&g_stats[tid],      (double)SSUM[tid]);
            atomicAdd(&g_stats[64 + tid], (double)SSQ[tid]);
        }
    }
}

// ---------------------------------------------------------------------------
// Elementwise / scatter kernels
// ---------------------------------------------------------------------------
__global__ void zero_kernel(float* a, int na, float* b, int nb,
                            float* c, int nc, int zstats, int initmax)
{
    int i = blockIdx.x * blockDim.x + threadIdx.x;
    if (a && i < na) a[i] = 0.f;
    if (b && i < nb) b[i] = 0.f;
    if (c && i < nc) c[i] = 0.f;
    if (zstats && i < 128) g_stats[i] = 0.0;
    if (initmax && i == 0) g_gmax = -3.402823466e38f;
}

// adp = softmax(feat @ W_adp) rowwise (3 logits)
__global__ void adp_kernel(const float* __restrict__ feat,
                           const float* __restrict__ Wadp,
                           float* __restrict__ adp, int n)
{
    __shared__ float w[192];
    int tid = threadIdx.x;
    if (tid < 192) w[tid] = Wadp[tid];
    __syncthreads();
    int r = blockIdx.x * blockDim.x + tid;
    if (r >= n) return;
    const float4* f = (const float4*)(feat + (size_t)r * 64);
    float l0 = 0.f, l1 = 0.f, l2 = 0.f;
#pragma unroll
    for (int c4 = 0; c4 < 16; c4++) {
        float4 v = f[c4];
        int c = c4 * 4;
        l0 += v.x * w[(c + 0) * 3 + 0] + v.y * w[(c + 1) * 3 + 0] +
              v.z * w[(c + 2) * 3 + 0] + v.w * w[(c + 3) * 3 + 0];
        l1 += v.x * w[(c + 0) * 3 + 1] + v.y * w[(c + 1) * 3 + 1] +
              v.z * w[(c + 2) * 3 + 1] + v.w * w[(c + 3) * 3 + 1];
        l2 += v.x * w[(c + 0) * 3 + 2] + v.y * w[(c + 1) * 3 + 2] +
              v.z * w[(c + 2) * 3 + 2] + v.w * w[(c + 3) * 3 + 2];
    }
    float m = fmaxf(l0, fmaxf(l1, l2));
    float e0 = expf(l0 - m), e1 = expf(l1 - m), e2 = expf(l2 - m);
    float inv = 1.f / (e0 + e1 + e2);
    adp[(size_t)r * 3 + 0] = e0 * inv;
    adp[(size_t)r * 3 + 1] = e1 * inv;
    adp[(size_t)r * 3 + 2] = e2 * inv;
}

// pw = relu(bn(X)); scatter-add pw into A[cl], counts into cnt[cl]
__global__ void bn_relu_scatter_k(const float* __restrict__ X,
                                  float* __restrict__ out,
                                  const int* __restrict__ cl,
                                  float* __restrict__ A, float* __restrict__ cnt,
                                  const float* __restrict__ gamma,
                                  const float* __restrict__ beta,
                                  int n, float invN)
{
    int idx = blockIdx.x * blockDim.x + threadIdx.x;
    if (idx >= n * 64) return;
    int r = idx >> 6, c = idx & 63;
    float v = fmaxf(bn_apply(X[idx], c, invN, gamma, beta), 0.f);
    out[idx] = v;
    int c0 = cl[r];
    atomicAdd(&A[(size_t)c0 * 64 + c], v);
    if (c == 0) atomicAdd(&cnt[c0], 1.f);
}

// pw2 = exp(X - gmax); scatter-add into B[cl]
__global__ void exp_scatter_k(const float* __restrict__ X,
                              float* __restrict__ out,
                              const int* __restrict__ cl,
                              float* __restrict__ B, int n)
{
    int idx = blockIdx.x * blockDim.x + threadIdx.x;
    if (idx >= n * 64) return;
    int r = idx >> 6, c = idx & 63;
    float v = expf(X[idx] - g_gmax);
    out[idx] = v;
    atomicAdd(&B[(size_t)cl[r] * 64 + c], v);
}

// pf = relu(bn(X)); w = PW / (B[cl] + 1e-6); scatter-add pf*w into A[cl]
__global__ void bn_mul_scatter_k(const float* __restrict__ X,
                                 const float* __restrict__ PW,
                                 const int* __restrict__ cl,
                                 const float* __restrict__ B,
                                 float* __restrict__ A,
                                 const float* __restrict__ gamma,
                                 const float* __restrict__ beta,
                                 int n, float invN)
{
    int idx = blockIdx.x * blockDim.x + threadIdx.x;
    if (idx >= n * 64) return;
    int r = idx >> 6, c = idx & 63;
    float pf = fmaxf(bn_apply(X[idx], c, invN, gamma, beta), 0.f);
    size_t co = (size_t)cl[r] * 64 + c;
    float w = PW[idx] / (B[co] + 1e-6f);
    atomicAdd(&A[co], pf * w);
}

// mix (+)= adp[:,s] * A[cl]
__global__ void mix_acc_k(float* __restrict__ mix,
                          const float* __restrict__ adp,
                          const float* __restrict__ A,
                          const int* __restrict__ cl,
                          int s, int first, int n)
{
    int idx = blockIdx.x * blockDim.x + threadIdx.x;
    if (idx >= n * 64) return;
    int r = idx >> 6, c = idx & 63;
    float m = adp[(size_t)r * 3 + s] * A[(size_t)cl[r] * 64 + c];
    if (first) mix[idx] = m; else mix[idx] += m;
}

// out = relu(bn(X))
__global__ void bn_relu_k(const float* __restrict__ X, float* __restrict__ out,
                          const float* __restrict__ gamma,
                          const float* __restrict__ beta, int n, float invN)
{
    int idx = blockIdx.x * blockDim.x + threadIdx.x;
    if (idx >= n * 64) return;
    int c = idx & 63;
    out[idx] = fmaxf(bn_apply(X[idx], c, invN, gamma, beta), 0.f);
}

// out = relu(bn(X)) + add
__global__ void bn_relu_add_k(const float* __restrict__ X,
                              const float* __restrict__ add,
                              float* __restrict__ out,
                              const float* __restrict__ gamma,
                              const float* __restrict__ beta, int n, float invN)
{
    int idx = blockIdx.x * blockDim.x + threadIdx.x;
    if (idx >= n * 64) return;
    int c = idx & 63;
    out[idx] = fmaxf(bn_apply(X[idx], c, invN, gamma, beta), 0.f) + add[idx];
}

// out = relu(bn(X) + res)
__global__ void final_k(const float* __restrict__ X,
                        const float* __restrict__ res,
                        float* __restrict__ out,
                        const float* __restrict__ gamma,
                        const float* __restrict__ beta, int n, float invN)
{
    int idx = blockIdx.x * blockDim.x + threadIdx.x;
    if (idx >= n * 64) return;
    int c = idx & 63;
    out[idx] = fmaxf(bn_apply(X[idx], c, invN, gamma, beta) + res[idx], 0.f);
}

// ---------------------------------------------------------------------------
// Host launcher
// ---------------------------------------------------------------------------
extern "C" void kernel_launch(void* const* d_in, const int* in_sizes, int n_in,
                              void* d_out, int out_size)
{
    const float* feat   = (const float*)d_in[0];
    const int*   cl[3]  = {(const int*)d_in[1], (const int*)d_in[2], (const int*)d_in[3]};
    const int*   nbr    = (const int*)d_in[4];
    const float* W_lw   = (const float*)d_in[5];
    const float* g_lw   = (const float*)d_in[6];
    const float* b_lw   = (const float*)d_in[7];
    const float* W_w    = (const float*)d_in[8];
    const float* W_proj = (const float*)d_in[9];
    const float* g_proj = (const float*)d_in[10];
    const float* b_proj = (const float*)d_in[11];
    const float* W_adp  = (const float*)d_in[12];
    const float* W_fuse = (const float*)d_in[13];
    const float* g_fuse = (const float*)d_in[14];
    const float* b_fuse = (const float*)d_in[15];
    const float* W_c1   = (const float*)d_in[16];
    const float* g_c1   = (const float*)d_in[17];
    const float* b_c1   = (const float*)d_in[18];
    const float* W_c2   = (const float*)d_in[19];
    const float* g_c2   = (const float*)d_in[20];
    const float* b_c2   = (const float*)d_in[21];

    const int   n    = in_sizes[0] / 64;
    const float invN = 1.f / (float)n;
    float* out = (float*)d_out;

    // scratch addresses
    float *bx, *bp, *bf, *cA, *cB, *cc, *adpb;
    cudaGetSymbolAddress((void**)&bx,   g_bufX);
    cudaGetSymbolAddress((void**)&bp,   g_bufP);
    cudaGetSymbolAddress((void**)&bf,   g_bufF);
    cudaGetSymbolAddress((void**)&cA,   g_cA);
    cudaGetSymbolAddress((void**)&cB,   g_cB);
    cudaGetSymbolAddress((void**)&cc,   g_ccnt);
    cudaGetSymbolAddress((void**)&adpb, g_adp);

    // allow >48KB dynamic smem
    cudaFuncSetAttribute(gemm64<0,1,0>, cudaFuncAttributeMaxDynamicSharedMemorySize, SMEM_BYTES);
    cudaFuncSetAttribute(gemm64<1,0,1>, cudaFuncAttributeMaxDynamicSharedMemorySize, SMEM_BYTES);
    cudaFuncSetAttribute(gemm64<2,1,0>, cudaFuncAttributeMaxDynamicSharedMemorySize, SMEM_BYTES);
    cudaFuncSetAttribute(conv27,        cudaFuncAttributeMaxDynamicSharedMemorySize, SMEM_BYTES);

    const int EW = (n * 64 + 255) / 256;   // elementwise grid
    const int GB = (n + 127) / 128;        // tile grid

    auto Z = [&](float* a, int na, float* b2, int nb, int zstats, int initmax) {
        int mx = na > nb ? na : nb;
        if (mx < 128) mx = 128;
        zero_kernel<<<(mx + 255) / 256, 256>>>(a, na, b2, nb, nullptr, 0, zstats, initmax);
    };

    // adaptive weights
    adp_kernel<<<(n + 255) / 256, 256>>>(feat, W_adp, adpb, n);

    // ---- three cluster branches ----
    for (int i = 0; i < 3; i++) {
        const int nci = NCL_H[i];
        // zero cluster sums + counts + stats, init gmax
        zero_kernel<<<(nci * 64 + 255) / 256, 256>>>(cA, nci * 64, cc, nci, nullptr, 0, 1, 1);
        // X1 = feat @ W_lw[i]  (+ BN stats)
        gemm64<0,1,0><<<GB, 128, SMEM_BYTES>>>(feat, nullptr, W_lw + i * 4096, bx,
                                               nullptr, nullptr, nullptr, n);
        // pw = relu(bn(X1)); scatter sums/counts
        bn_relu_scatter_k<<<EW, 256>>>(bx, bp, cl[i], cA, cc,
                                       g_lw + i * 64, b_lw + i * 64, n, invN);
        // X2 = (pw - mean[cl]) @ W_w[i]  (+ global max)
        gemm64<1,0,1><<<GB, 128, SMEM_BYTES>>>(bp, nullptr, W_w + i * 4096, bx,
                                               cl[i], cA, cc, n);
        // zero A (reuse for pfeat sums), B (denoms), stats (for proj BN)
        Z(cA, nci * 64, cB, nci * 64, 1, 0);
        // pw2 = exp(X2 - gmax); scatter denom
        exp_scatter_k<<<EW, 256>>>(bx, bp, cl[i], cB, n);
        // X3 = feat @ W_proj[i]  (+ BN stats)
        gemm64<0,1,0><<<GB, 128, SMEM_BYTES>>>(feat, nullptr, W_proj + i * 4096, bx,
                                               nullptr, nullptr, nullptr, n);
        // pf = relu(bn(X3)); scatter pf * pw2/denom into A
        bn_mul_scatter_k<<<EW, 256>>>(bx, bp, cl[i], cB, cA,
                                      g_proj + i * 64, b_proj + i * 64, n, invN);
        // mix (+)= adp[:,i] * A[cl]   (mix lives in d_out)
        mix_acc_k<<<EW, 256>>>(out, adpb, cA, cl[i], i, (i == 0) ? 1 : 0, n);
    }

    // ---- f_last ----
    Z(nullptr, 0, nullptr, 0, 1, 0);
    gemm64<0,1,0><<<GB, 128, SMEM_BYTES>>>(feat, nullptr, W_proj + 3 * 4096, bx,
                                           nullptr, nullptr, nullptr, n);
    bn_relu_k<<<EW, 256>>>(bx, bp, g_proj + 192, b_proj + 192, n, invN); // f_last -> bp

    // ---- fuse: [f_last | mix] @ W_fuse ----
    Z(nullptr, 0, nullptr, 0, 1, 0);
    gemm64<2,1,0><<<GB, 128, SMEM_BYTES>>>(bp, out, W_fuse, bx,
                                           nullptr, nullptr, nullptr, n);
    bn_relu_add_k<<<EW, 256>>>(bx, feat, bf, g_fuse, b_fuse, n, invN);   // fused -> bf

    // ---- conv1 -> bn -> relu ----
    Z(nullptr, 0, nullptr, 0, 1, 0);
    conv27<<<GB, 128, SMEM_BYTES>>>(bf, nbr, W_c1, bx, n);
    bn_relu_k<<<EW, 256>>>(bx, out, g_c1, b_c1, n, invN);                // h1 -> out

    // ---- conv2 -> bn ; out = relu(h + fused) ----
    Z(nullptr, 0, nullptr, 0, 1, 0);
    conv27<<<GB, 128, SMEM_BYTES>>>(out, nbr, W_c2, bx, n);
    final_k<<<EW, 256>>>(bx, bf, out, g_c2, b_c2, n, invN);
}

// round 3
// speedup vs baseline: 1.1260x; 1.1260x over previous
#include <cuda_runtime.h>
#include <math.h>

// ---------------------------------------------------------------------------
// Problem constants
// ---------------------------------------------------------------------------
#define NMAX 500000
#define CCH  64
#define KTAP 27

static const int NCL_H[3] = {4096, 32768, 131072};

// ---------------------------------------------------------------------------
// Device scratch
// ---------------------------------------------------------------------------
__device__ float  g_bufX[NMAX * CCH];
__device__ float  g_bufP[NMAX * CCH];
__device__ float  g_bufF[NMAX * CCH];
__device__ float  g_cA[131072 * CCH];
__device__ float  g_cB[131072 * CCH];
__device__ float  g_ccnt[131072];
__device__ float  g_adp[NMAX * 3];
__device__ double g_stats[2 * CCH];
__device__ float  g_gmax;

// ---------------------------------------------------------------------------
// Helpers
// ---------------------------------------------------------------------------
__device__ __forceinline__ void atomicMaxFloat(float* addr, float val) {
    int old = __float_as_int(*addr);
    while (__int_as_float(old) < val) {
        int assumed = old;
        old = atomicCAS((int*)addr, assumed, __float_as_int(val));
        if (old == assumed) break;
    }
}

__device__ __forceinline__ unsigned f2tf32(float x) {
    unsigned r;
    asm("cvt.rna.tf32.f32 %0, %1;" : "=r"(r) : "f"(x));
    return r;
}

__device__ __forceinline__ void mma_tf32(float d[4], const unsigned a[4],
                                         const unsigned b[2]) {
    asm volatile(
        "mma.sync.aligned.m16n8k8.row.col.f32.tf32.tf32.f32 "
        "{%0,%1,%2,%3}, {%4,%5,%6,%7}, {%8,%9}, {%0,%1,%2,%3};"
        : "+f"(d[0]), "+f"(d[1]), "+f"(d[2]), "+f"(d[3])
        : "r"(a[0]), "r"(a[1]), "r"(a[2]), "r"(a[3]), "r"(b[0]), "r"(b[1]));
}

__device__ __forceinline__ float bn_apply(float x, int c, float invN,
                                          const float* __restrict__ gamma,
                                          const float* __restrict__ beta) {
    float mu  = (float)g_stats[c] * invN;
    float ex2 = (float)g_stats[CCH + c] * invN;
    float var = ex2 - mu * mu;
    float rs  = rsqrtf(var + 1e-3f);
    return (x - mu) * rs * gamma[c] + beta[c];
}

// ---------------------------------------------------------------------------
// Shared-memory layout (dynamic)
//   XS : 128 rows x 64 cols tf32, stride 68 words
//   WS : 64  rows x 64 cols tf32, stride 68 words
// ---------------------------------------------------------------------------
#define XST 68
#define SM_XS (128 * XST)
#define SM_WS (64 * XST)
#define SMEM_FLOATS (SM_XS + SM_WS + 160)
#define SMEM_BYTES  (SMEM_FLOATS * 4)

// ---------------------------------------------------------------------------
// Load helpers (all 128 threads cooperate)
// ---------------------------------------------------------------------------
template <int MODE>
__device__ __forceinline__ void load_x_tile(
    unsigned* XSu, const float* __restrict__ Xp, int base, int tid, int nrows,
    const int* __restrict__ cl, const float* __restrict__ csum,
    const float* __restrict__ ccnt)
{
    int n = base + tid;
    if (n < nrows) {
        const float4* src = (const float4*)(Xp + (size_t)n * 64);
        float minv = 0.f;
        const float4* mp = nullptr;
        if (MODE == 1) {
            int c0 = cl[n];
            minv = 1.f / fmaxf(ccnt[c0], 1.f);
            mp = (const float4*)(csum + (size_t)c0 * 64);
        }
#pragma unroll
        for (int c4 = 0; c4 < 16; c4++) {
            float4 v = src[c4];
            if (MODE == 1) {
                float4 m = mp[c4];
                v.x -= m.x * minv; v.y -= m.y * minv;
                v.z -= m.z * minv; v.w -= m.w * minv;
            }
            uint4 u;
            u.x = f2tf32(v.x); u.y = f2tf32(v.y);
            u.z = f2tf32(v.z); u.w = f2tf32(v.w);
            *(uint4*)&XSu[tid * XST + c4 * 4] = u;
        }
    } else {
        uint4 z = make_uint4(0, 0, 0, 0);
#pragma unroll
        for (int c4 = 0; c4 < 16; c4++)
            *(uint4*)&XSu[tid * XST + c4 * 4] = z;
    }
}

__device__ __forceinline__ void load_x_gather(
    unsigned* XSu, const float* __restrict__ F, const int* __restrict__ nbr,
    int base, int tid, int k, int nrows)
{
    int n = base + tid;
    if (n < nrows) {
        int idx = __ldg(&nbr[(size_t)n * KTAP + k]);
        const float4* src = (const float4*)(F + (size_t)idx * 64);
#pragma unroll
        for (int c4 = 0; c4 < 16; c4++) {
            float4 v = __ldg(&src[c4]);
            uint4 u;
            u.x = f2tf32(v.x); u.y = f2tf32(v.y);
            u.z = f2tf32(v.z); u.w = f2tf32(v.w);
            *(uint4*)&XSu[tid * XST + c4 * 4] = u;
        }
    } else {
        uint4 z = make_uint4(0, 0, 0, 0);
#pragma unroll
        for (int c4 = 0; c4 < 16; c4++)
            *(uint4*)&XSu[tid * XST + c4 * 4] = z;
    }
}

__device__ __forceinline__ void load_w_tile(unsigned* WSu,
                                            const float* __restrict__ W, int tid)
{
    int r = tid >> 1, h = (tid & 1) * 32;
    const float4* src = (const float4*)(W + r * 64 + h);
#pragma unroll
    for (int c4 = 0; c4 < 8; c4++) {
        float4 v = src[c4];
        uint4 u;
        u.x = f2tf32(v.x); u.y = f2tf32(v.y);
        u.z = f2tf32(v.z); u.w = f2tf32(v.w);
        *(uint4*)&WSu[r * XST + h + c4 * 4] = u;
    }
}

// 8 k-tiles of mma over one (XS, WS) pair, accumulate into d[2][8][4]
__device__ __forceinline__ void mma_block(float d[2][8][4],
                                          const unsigned* XSu,
                                          const unsigned* WSu,
                                          int w, int g, int t)
{
#pragma unroll
    for (int kt = 0; kt < 8; kt++) {
        int k0 = kt * 8;
        unsigned b[8][2];
#pragma unroll
        for (int nt = 0; nt < 8; nt++) {
            b[nt][0] = WSu[(k0 + t) * XST + nt * 8 + g];
            b[nt][1] = WSu[(k0 + t + 4) * XST + nt * 8 + g];
        }
#pragma unroll
        for (int mt = 0; mt < 2; mt++) {
            int m0 = w * 32 + mt * 16;
            unsigned a[4];
            a[0] = XSu[(m0 + g) * XST + k0 + t];
            a[1] = XSu[(m0 + g + 8) * XST + k0 + t];
            a[2] = XSu[(m0 + g) * XST + k0 + t + 4];
            a[3] = XSu[(m0 + g + 8) * XST + k0 + t + 4];
#pragma unroll
            for (int nt = 0; nt < 8; nt++) mma_tf32(d[mt][nt], a, b[nt]);
        }
    }
}

// epilogue: store + optional stats/max
template <int STATS, int MAXRED>
__device__ __forceinline__ void epilogue(float d[2][8][4], float* __restrict__ Y,
                                         float* SSUM, float* SSQ, float* RED,
                                         int base, int tid, int nrows)
{
    const int lane = tid & 31, w = tid >> 5, g = lane >> 2, t = lane & 3;
#pragma unroll
    for (int mt = 0; mt < 2; mt++) {
        int r0 = base + w * 32 + mt * 16 + g;
        int r1 = r0 + 8;
#pragma unroll
        for (int nt = 0; nt < 8; nt++) {
            int c0 = nt * 8 + 2 * t;
            if (r0 < nrows)
                *(float2*)(Y + (size_t)r0 * 64 + c0) =
                    make_float2(d[mt][nt][0], d[mt][nt][1]);
            if (r1 < nrows)
                *(float2*)(Y + (size_t)r1 * 64 + c0) =
                    make_float2(d[mt][nt][2], d[mt][nt][3]);
        }
    }
    if (STATS) {
#pragma unroll
        for (int nt = 0; nt < 8; nt++) {
            float s0 = 0.f, s1 = 0.f, q0 = 0.f, q1 = 0.f;
#pragma unroll
            for (int mt = 0; mt < 2; mt++) {
                int r0 = base + w * 32 + mt * 16 + g;
                if (r0 < nrows) {
                    s0 += d[mt][nt][0]; q0 += d[mt][nt][0] * d[mt][nt][0];
                    s1 += d[mt][nt][1]; q1 += d[mt][nt][1] * d[mt][nt][1];
                }
                if (r0 + 8 < nrows) {
                    s0 += d[mt][nt][2]; q0 += d[mt][nt][2] * d[mt][nt][2];
                    s1 += d[mt][nt][3]; q1 += d[mt][nt][3] * d[mt][nt][3];
                }
            }
            int c0 = nt * 8 + 2 * t;
            atomicAdd(&SSUM[c0], s0);     atomicAdd(&SSUM[c0 + 1], s1);
            atomicAdd(&SSQ[c0], q0);      atomicAdd(&SSQ[c0 + 1], q1);
        }
        __syncthreads();
        if (tid < 64) {
            atomicAdd(&g_stats[tid],      (double)SSUM[tid]);
            atomicAdd(&g_stats[64 + tid], (double)SSQ[tid]);
        }
    }
    if (MAXRED) {
        float m = -3.402823466e38f;
#pragma unroll
        for (int mt = 0; mt < 2; mt++) {
            int r0 = base + w * 32 + mt * 16 + g;
#pragma unroll
            for (int nt = 0; nt < 8; nt++) {
                if (r0 < nrows)     m = fmaxf(m, fmaxf(d[mt][nt][0], d[mt][nt][1]));
                if (r0 + 8 < nrows) m = fmaxf(m, fmaxf(d[mt][nt][2], d[mt][nt][3]));
            }
        }
#pragma unroll
        for (int o = 16; o > 0; o >>= 1)
            m = fmaxf(m, __shfl_xor_sync(0xffffffffu, m, o));
        if (lane == 0) RED[w] = m;
        __syncthreads();
        if (tid == 0) {
            m = fmaxf(fmaxf(RED[0], RED[1]), fmaxf(RED[2], RED[3]));
            atomicMaxFloat(&g_gmax, m);
        }
    }
}

// ---------------------------------------------------------------------------
// Tiled 64-wide GEMM (tf32 tensor cores)
// ---------------------------------------------------------------------------
template <int MODE, int STATS, int MAXRED>
__global__ void __launch_bounds__(128) gemm64t(
    const float* __restrict__ X, const float* __restrict__ X2,
    const float* __restrict__ W, float* __restrict__ Y,
    const int* __restrict__ cl, const float* __restrict__ csum,
    const float* __restrict__ ccnt, int nrows)
{
    extern __shared__ float sm[];
    unsigned* XSu = (unsigned*)sm;
    unsigned* WSu = (unsigned*)(sm + SM_XS);
    float* SSUM = sm + SM_XS + SM_WS;
    float* SSQ  = SSUM + 64;
    float* RED  = SSQ + 64;

    const int tid  = threadIdx.x;
    const int base = blockIdx.x * 128;
    const int lane = tid & 31, w = tid >> 5, g = lane >> 2, t = lane & 3;

    if (STATS && tid < 64) { SSUM[tid] = 0.f; SSQ[tid] = 0.f; }

    float d[2][8][4];
#pragma unroll
    for (int mt = 0; mt < 2; mt++)
#pragma unroll
        for (int nt = 0; nt < 8; nt++)
#pragma unroll
            for (int i = 0; i < 4; i++) d[mt][nt][i] = 0.f;

    const int NP = (MODE == 2) ? 2 : 1;
    for (int p = 0; p < NP; p++) {
        __syncthreads();
        load_w_tile(WSu, W + p * 4096, tid);
        const float* Xp = (MODE == 2 && p == 1) ? X2 : X;
        load_x_tile<MODE == 1 ? 1 : 0>(XSu, Xp, base, tid, nrows, cl, csum, ccnt);
        __syncthreads();
        mma_block(d, XSu, WSu, w, g, t);
    }
    __syncthreads();
    epilogue<STATS, MAXRED>(d, Y, SSUM, SSQ, RED, base, tid, nrows);
}

// ---------------------------------------------------------------------------
// 27-tap submanifold conv (tf32 tensor cores) + BN stats
// ---------------------------------------------------------------------------
__global__ void __launch_bounds__(128) conv27t(
    const float* __restrict__ F, const int* __restrict__ nbr,
    const float* __restrict__ Wc, float* __restrict__ Y, int nrows)
{
    extern __shared__ float sm[];
    unsigned* XSu = (unsigned*)sm;
    unsigned* WSu = (unsigned*)(sm + SM_XS);
    float* SSUM = sm + SM_XS + SM_WS;
    float* SSQ  = SSUM + 64;
    float* RED  = SSQ + 64;

    const int tid  = threadIdx.x;
    const int base = blockIdx.x * 128;
    const int lane = tid & 31, w = tid >> 5, g = lane >> 2, t = lane & 3;

    if (tid < 64) { SSUM[tid] = 0.f; SSQ[tid] = 0.f; }

    float d[2][8][4];
#pragma unroll
    for (int mt = 0; mt < 2; mt++)
#pragma unroll
        for (int nt = 0; nt < 8; nt++)
#pragma unroll
            for (int i = 0; i < 4; i++) d[mt][nt][i] = 0.f;

    for (int k = 0; k < KTAP; k++) {
        __syncthreads();
        load_w_tile(WSu, Wc + k * 4096, tid);
        load_x_gather(XSu, F, nbr, base, tid, k, nrows);
        __syncthreads();
        mma_block(d, XSu, WSu, w, g, t);
    }
    __syncthreads();
    epilogue<1, 0>(d, Y, SSUM, SSQ, RED, base, tid, nrows);
}

// ---------------------------------------------------------------------------
// Elementwise / scatter kernels
// ---------------------------------------------------------------------------
__global__ void zero_kernel(float* a, int na, float* b, int nb,
                            int zstats, int initmax)
{
    int i = blockIdx.x * blockDim.x + threadIdx.x;
    if (a && i < na) a[i] = 0.f;
    if (b && i < nb) b[i] = 0.f;
    if (zstats && i < 128) g_stats[i] = 0.0;
    if (initmax && i == 0) g_gmax = -3.402823466e38f;
}

__global__ void adp_kernel(const float* __restrict__ feat,
                           const float* __restrict__ Wadp,
                           float* __restrict__ adp, int n)
{
    __shared__ float w[192];
    int tid = threadIdx.x;
    if (tid < 192) w[tid] = Wadp[tid];
    __syncthreads();
    int r = blockIdx.x * blockDim.x + tid;
    if (r >= n) return;
    const float4* f = (const float4*)(feat + (size_t)r * 64);
    float l0 = 0.f, l1 = 0.f, l2 = 0.f;
#pragma unroll
    for (int c4 = 0; c4 < 16; c4++) {
        float4 v = f[c4];
        int c = c4 * 4;
        l0 += v.x * w[(c + 0) * 3 + 0] + v.y * w[(c + 1) * 3 + 0] +
              v.z * w[(c + 2) * 3 + 0] + v.w * w[(c + 3) * 3 + 0];
        l1 += v.x * w[(c + 0) * 3 + 1] + v.y * w[(c + 1) * 3 + 1] +
              v.z * w[(c + 2) * 3 + 1] + v.w * w[(c + 3) * 3 + 1];
        l2 += v.x * w[(c + 0) * 3 + 2] + v.y * w[(c + 1) * 3 + 2] +
              v.z * w[(c + 2) * 3 + 2] + v.w * w[(c + 3) * 3 + 2];
    }
    float m = fmaxf(l0, fmaxf(l1, l2));
    float e0 = expf(l0 - m), e1 = expf(l1 - m), e2 = expf(l2 - m);
    float inv = 1.f / (e0 + e1 + e2);
    adp[(size_t)r * 3 + 0] = e0 * inv;
    adp[(size_t)r * 3 + 1] = e1 * inv;
    adp[(size_t)r * 3 + 2] = e2 * inv;
}

__global__ void bn_relu_scatter_k(const float* __restrict__ X,
                                  float* __restrict__ out,
                                  const int* __restrict__ cl,
                                  float* __restrict__ A, float* __restrict__ cnt,
                                  const float* __restrict__ gamma,
                                  const float* __restrict__ beta,
                                  int n, float invN)
{
    int idx = blockIdx.x * blockDim.x + threadIdx.x;
    if (idx >= n * 64) return;
    int r = idx >> 6, c = idx & 63;
    float v = fmaxf(bn_apply(X[idx], c, invN, gamma, beta), 0.f);
    out[idx] = v;
    int c0 = cl[r];
    atomicAdd(&A[(size_t)c0 * 64 + c], v);
    if (c == 0) atomicAdd(&cnt[c0], 1.f);
}

__global__ void exp_scatter_k(const float* __restrict__ X,
                              float* __restrict__ out,
                              const int* __restrict__ cl,
                              float* __restrict__ B, int n)
{
    int idx = blockIdx.x * blockDim.x + threadIdx.x;
    if (idx >= n * 64) return;
    int r = idx >> 6;
    float v = expf(X[idx] - g_gmax);
    out[idx] = v;
    atomicAdd(&B[(size_t)cl[r] * 64 + (idx & 63)], v);
}

__global__ void bn_mul_scatter_k(const float* __restrict__ X,
                                 const float* __restrict__ PW,
                                 const int* __restrict__ cl,
                                 const float* __restrict__ B,
                                 float* __restrict__ A,
                                 const float* __restrict__ gamma,
                                 const float* __restrict__ beta,
                                 int n, float invN)
{
    int idx = blockIdx.x * blockDim.x + threadIdx.x;
    if (idx >= n * 64) return;
    int r = idx >> 6, c = idx & 63;
    float pf = fmaxf(bn_apply(X[idx], c, invN, gamma, beta), 0.f);
    size_t co = (size_t)cl[r] * 64 + c;
    float w = PW[idx] / (B[co] + 1e-6f);
    atomicAdd(&A[co], pf * w);
}

__global__ void mix_acc_k(float* __restrict__ mix,
                          const float* __restrict__ adp,
                          const float* __restrict__ A,
                          const int* __restrict__ cl,
                          int s, int first, int n)
{
    int idx = blockIdx.x * blockDim.x + threadIdx.x;
    if (idx >= n * 64) return;
    int r = idx >> 6, c = idx & 63;
    float m = adp[(size_t)r * 3 + s] * A[(size_t)cl[r] * 64 + c];
    if (first) mix[idx] = m; else mix[idx] += m;
}

__global__ void bn_relu_k(const float* __restrict__ X, float* __restrict__ out,
                          const float* __restrict__ gamma,
                          const float* __restrict__ beta, int n, float invN)
{
    int idx = blockIdx.x * blockDim.x + threadIdx.x;
    if (idx >= n * 64) return;
    int c = idx & 63;
    out[idx] = fmaxf(bn_apply(X[idx], c, invN, gamma, beta), 0.f);
}

__global__ void bn_relu_add_k(const float* __restrict__ X,
                              const float* __restrict__ add,
                              float* __restrict__ out,
                              const float* __restrict__ gamma,
                              const float* __restrict__ beta, int n, float invN)
{
    int idx = blockIdx.x * blockDim.x + threadIdx.x;
    if (idx >= n * 64) return;
    int c = idx & 63;
    out[idx] = fmaxf(bn_apply(X[idx], c, invN, gamma, beta), 0.f) + add[idx];
}

__global__ void final_k(const float* __restrict__ X,
                        const float* __restrict__ res,
                        float* __restrict__ out,
                        const float* __restrict__ gamma,
                        const float* __restrict__ beta, int n, float invN)
{
    int idx = blockIdx.x * blockDim.x + threadIdx.x;
    if (idx >= n * 64) return;
    int c = idx & 63;
    out[idx] = fmaxf(bn_apply(X[idx], c, invN, gamma, beta) + res[idx], 0.f);
}

// ---------------------------------------------------------------------------
// Host launcher
// ---------------------------------------------------------------------------
extern "C" void kernel_launch(void* const* d_in, const int* in_sizes, int n_in,
                              void* d_out, int out_size)
{
    const float* feat   = (const float*)d_in[0];
    const int*   cl[3]  = {(const int*)d_in[1], (const int*)d_in[2], (const int*)d_in[3]};
    const int*   nbr    = (const int*)d_in[4];
    const float* W_lw   = (const float*)d_in[5];
    const float* g_lw   = (const float*)d_in[6];
    const float* b_lw   = (const float*)d_in[7];
    const float* W_w    = (const float*)d_in[8];
    const float* W_proj = (const float*)d_in[9];
    const float* g_proj = (const float*)d_in[10];
    const float* b_proj = (const float*)d_in[11];
    const float* W_adp  = (const float*)d_in[12];
    const float* W_fuse = (const float*)d_in[13];
    const float* g_fuse = (const float*)d_in[14];
    const float* b_fuse = (const float*)d_in[15];
    const float* W_c1   = (const float*)d_in[16];
    const float* g_c1   = (const float*)d_in[17];
    const float* b_c1   = (const float*)d_in[18];
    const float* W_c2   = (const float*)d_in[19];
    const float* g_c2   = (const float*)d_in[20];
    const float* b_c2   = (const float*)d_in[21];

    const int   n    = in_sizes[0] / 64;
    const float invN = 1.f / (float)n;
    float* out = (float*)d_out;

    float *bx, *bp, *bf, *cA, *cB, *cc, *adpb;
    cudaGetSymbolAddress((void**)&bx,   g_bufX);
    cudaGetSymbolAddress((void**)&bp,   g_bufP);
    cudaGetSymbolAddress((void**)&bf,   g_bufF);
    cudaGetSymbolAddress((void**)&cA,   g_cA);
    cudaGetSymbolAddress((void**)&cB,   g_cB);
    cudaGetSymbolAddress((void**)&cc,   g_ccnt);
    cudaGetSymbolAddress((void**)&adpb, g_adp);

    cudaFuncSetAttribute(gemm64t<0,1,0>, cudaFuncAttributeMaxDynamicSharedMemorySize, SMEM_BYTES);
    cudaFuncSetAttribute(gemm64t<1,0,1>, cudaFuncAttributeMaxDynamicSharedMemorySize, SMEM_BYTES);
    cudaFuncSetAttribute(gemm64t<2,1,0>, cudaFuncAttributeMaxDynamicSharedMemorySize, SMEM_BYTES);
    cudaFuncSetAttribute(conv27t,        cudaFuncAttributeMaxDynamicSharedMemorySize, SMEM_BYTES);

    const int EW = (n * 64 + 255) / 256;
    const int GB = (n + 127) / 128;

    auto Zs = [&](int zstats) {
        zero_kernel<<<1, 256>>>(nullptr, 0, nullptr, 0, zstats, 0);
    };

    adp_kernel<<<(n + 255) / 256, 256>>>(feat, W_adp, adpb, n);

    for (int i = 0; i < 3; i++) {
        const int nci = NCL_H[i];
        zero_kernel<<<(nci * 64 + 255) / 256, 256>>>(cA, nci * 64, cc, nci, 1, 1);
        gemm64t<0,1,0><<<GB, 128, SMEM_BYTES>>>(feat, nullptr, W_lw + i * 4096, bx,
                                                nullptr, nullptr, nullptr, n);
        bn_relu_scatter_k<<<EW, 256>>>(bx, bp, cl[i], cA, cc,
                                       g_lw + i * 64, b_lw + i * 64, n, invN);
        gemm64t<1,0,1><<<GB, 128, SMEM_BYTES>>>(bp, nullptr, W_w + i * 4096, bx,
                                                cl[i], cA, cc, n);
        zero_kernel<<<(nci * 64 + 255) / 256, 256>>>(cA, nci * 64, cB, nci * 64, 1, 0);
        exp_scatter_k<<<EW, 256>>>(bx, bp, cl[i], cB, n);
        gemm64t<0,1,0><<<GB, 128, SMEM_BYTES>>>(feat, nullptr, W_proj + i * 4096, bx,
                                                nullptr, nullptr, nullptr, n);
        bn_mul_scatter_k<<<EW, 256>>>(bx, bp, cl[i], cB, cA,
                                      g_proj + i * 64, b_proj + i * 64, n, invN);
        mix_acc_k<<<EW, 256>>>(out, adpb, cA, cl[i], i, (i == 0) ? 1 : 0, n);
    }

    // f_last
    Zs(1);
    gemm64t<0,1,0><<<GB, 128, SMEM_BYTES>>>(feat, nullptr, W_proj + 3 * 4096, bx,
                                            nullptr, nullptr, nullptr, n);
    bn_relu_k<<<EW, 256>>>(bx, bp, g_proj + 192, b_proj + 192, n, invN);

    // fuse
    Zs(1);
    gemm64t<2,1,0><<<GB, 128, SMEM_BYTES>>>(bp, out, W_fuse, bx,
                                            nullptr, nullptr, nullptr, n);
    bn_relu_add_k<<<EW, 256>>>(bx, feat, bf, g_fuse, b_fuse, n, invN);

    // conv1 -> bn -> relu
    Zs(1);
    conv27t<<<GB, 128, SMEM_BYTES>>>(bf, nbr, W_c1, bx, n);
    bn_relu_k<<<EW, 256>>>(bx, out, g_c1, b_c1, n, invN);

    // conv2 -> bn ; relu(h + fused)
    Zs(1);
    conv27t<<<GB, 128, SMEM_BYTES>>>(out, nbr, W_c2, bx, n);
    final_k<<<EW, 256>>>(bx, bf, out, g_c2, b_c2, n, invN);
}

// round 4
// speedup vs baseline: 1.5562x; 1.3821x over previous
#include <cuda_runtime.h>
#include <math.h>

#define NMAX 500000
#define CCH  64
#define KTAP 27

static const int NCL_H[3] = {4096, 32768, 131072};

// ---------------------------------------------------------------------------
// Device scratch
// ---------------------------------------------------------------------------
__device__ float  g_bufX[NMAX * CCH];       // gemm/conv output scratch
__device__ float  g_bufP[NMAX * CCH];       // pw / f_last / h1 scratch
__device__ float  g_bufF[NMAX * CCH];       // fused residual
__device__ float  g_sum[131072 * CCH];      // per-cluster pw sums
__device__ float  g_den[131072 * CCH];      // per-cluster softmax denoms
__device__ float  g_pf0[4096 * CCH];        // branch-0 pooled feats
__device__ float  g_pf1[32768 * CCH];       // branch-1 pooled feats
__device__ float  g_pf2[131072 * CCH];      // branch-2 pooled feats
__device__ float  g_ccnt[131072];
__device__ float  g_adpw[NMAX * 3];
__device__ float  g_S[CCH * CCH];           // feat^T feat (tf32-rounded inputs)
__device__ float  g_m[CCH];                 // col sums of tf32-rounded feat
__device__ float  g_bnc[8 * 128];           // 8 slots x (scale[64], shift[64])
__device__ double g_stats[2 * CCH];         // runtime BN stats (fuse/convs)
__device__ float  g_gmax;

// ---------------------------------------------------------------------------
// Helpers
// ---------------------------------------------------------------------------
__device__ __forceinline__ void atomicMaxFloat(float* addr, float val) {
    int old = __float_as_int(*addr);
    while (__int_as_float(old) < val) {
        int assumed = old;
        old = atomicCAS((int*)addr, assumed, __float_as_int(val));
        if (old == assumed) break;
    }
}

__device__ __forceinline__ unsigned f2tf32(float x) {
    unsigned r;
    asm("cvt.rna.tf32.f32 %0, %1;" : "=r"(r) : "f"(x));
    return r;
}

__device__ __forceinline__ void mma_tf32(float d[4], const unsigned a[4],
                                         const unsigned b[2]) {
    asm volatile(
        "mma.sync.aligned.m16n8k8.row.col.f32.tf32.tf32.f32 "
        "{%0,%1,%2,%3}, {%4,%5,%6,%7}, {%8,%9}, {%0,%1,%2,%3};"
        : "+f"(d[0]), "+f"(d[1]), "+f"(d[2]), "+f"(d[3])
        : "r"(a[0]), "r"(a[1]), "r"(a[2]), "r"(a[3]), "r"(b[0]), "r"(b[1]));
}

// ---------------------------------------------------------------------------
// GEMM smem layout: XS 128x68, WS 64x68, epi scratch
// ---------------------------------------------------------------------------
#define XST 68
#define SM_XS (128 * XST)
#define SM_WS (64 * XST)
#define GEMM_SM_FLOATS (SM_XS + SM_WS + 320)
#define GEMM_SM_BYTES  (GEMM_SM_FLOATS * 4)

// conv smem: double-buffered raw-float tiles
#define CSM_X (128 * XST)
#define CSM_W (64 * XST)
#define CONV_SM_FLOATS (2 * CSM_X + 2 * CSM_W + 320)
#define CONV_SM_BYTES  (CONV_SM_FLOATS * 4)

// ---------------------------------------------------------------------------
// Parameter pack for the unified GEMM kernel
// ---------------------------------------------------------------------------
struct GP {
    const float* X;  const float* X2;
    const float* W;  float* Y;
    const int* cl;   const float* csum; const float* ccnt;
    const float* bnc;          // 128 floats: scale, shift
    float* scat;  float* cnt;
    const float* PW; const float* denom;
    // MODE2 mix-on-the-fly:
    const float* adp;
    const int *cl0, *cl1, *cl2;
    const float *pf0, *pf1, *pf2;
    int nrows;
};

// ---------------------------------------------------------------------------
// Loaders (128 threads, one row each)
// ---------------------------------------------------------------------------
template <int MODE, int EPI>
__device__ __forceinline__ void load_x_tile(unsigned* XSu, const GP& p,
                                            int pidx, int base, int tid)
{
    int n = base + tid;
    if (n < p.nrows) {
        if (MODE == 2 && pidx == 1) {
            // mix = sum_s adp[s] * pf_s[cl_s[n]]
            float a0 = p.adp[(size_t)n * 3 + 0];
            float a1 = p.adp[(size_t)n * 3 + 1];
            float a2 = p.adp[(size_t)n * 3 + 2];
            const float4* q0 = (const float4*)(p.pf0 + (size_t)p.cl0[n] * 64);
            const float4* q1 = (const float4*)(p.pf1 + (size_t)p.cl1[n] * 64);
            const float4* q2 = (const float4*)(p.pf2 + (size_t)p.cl2[n] * 64);
#pragma unroll
            for (int c4 = 0; c4 < 16; c4++) {
                float4 v0 = q0[c4], v1 = q1[c4], v2 = q2[c4];
                uint4 u;
                u.x = f2tf32(a0 * v0.x + a1 * v1.x + a2 * v2.x);
                u.y = f2tf32(a0 * v0.y + a1 * v1.y + a2 * v2.y);
                u.z = f2tf32(a0 * v0.z + a1 * v1.z + a2 * v2.z);
                u.w = f2tf32(a0 * v0.w + a1 * v1.w + a2 * v2.w);
                *(uint4*)&XSu[tid * XST + c4 * 4] = u;
            }
        } else {
            const float* Xp = (MODE == 2) ? p.X : ((MODE == 2) ? p.X2 : p.X);
            const float4* src = (const float4*)(Xp + (size_t)n * 64);
            float minv = 0.f;
            const float4* mp = nullptr;
            if (MODE == 1) {
                int c0 = p.cl[n];
                minv = 1.f / fmaxf(p.ccnt[c0], 1.f);
                mp = (const float4*)(p.csum + (size_t)c0 * 64);
            }
            if (EPI == 2) atomicAdd(&p.cnt[p.cl[n]], 1.f);
#pragma unroll
            for (int c4 = 0; c4 < 16; c4++) {
                float4 v = src[c4];
                if (MODE == 1) {
                    float4 m = mp[c4];
                    v.x -= m.x * minv; v.y -= m.y * minv;
                    v.z -= m.z * minv; v.w -= m.w * minv;
                }
                uint4 u;
                u.x = f2tf32(v.x); u.y = f2tf32(v.y);
                u.z = f2tf32(v.z); u.w = f2tf32(v.w);
                *(uint4*)&XSu[tid * XST + c4 * 4] = u;
            }
        }
    } else {
        uint4 z = make_uint4(0, 0, 0, 0);
#pragma unroll
        for (int c4 = 0; c4 < 16; c4++)
            *(uint4*)&XSu[tid * XST + c4 * 4] = z;
    }
}

__device__ __forceinline__ void load_w_tile(unsigned* WSu,
                                            const float* __restrict__ W, int tid)
{
    int r = tid >> 1, h = (tid & 1) * 32;
    const float4* src = (const float4*)(W + r * 64 + h);
#pragma unroll
    for (int c4 = 0; c4 < 8; c4++) {
        float4 v = src[c4];
        uint4 u;
        u.x = f2tf32(v.x); u.y = f2tf32(v.y);
        u.z = f2tf32(v.z); u.w = f2tf32(v.w);
        *(uint4*)&WSu[r * XST + h + c4 * 4] = u;
    }
}

// full 64-K mma over (XS, WS) into d[2][8][4]
__device__ __forceinline__ void mma_block(float d[2][8][4],
                                          const unsigned* XSu,
                                          const unsigned* WSu,
                                          int w, int g, int t)
{
#pragma unroll
    for (int kt = 0; kt < 8; kt++) {
        int k0 = kt * 8;
        unsigned b[8][2];
#pragma unroll
        for (int nt = 0; nt < 8; nt++) {
            b[nt][0] = WSu[(k0 + t) * XST + nt * 8 + g];
            b[nt][1] = WSu[(k0 + t + 4) * XST + nt * 8 + g];
        }
#pragma unroll
        for (int mt = 0; mt < 2; mt++) {
            int m0 = w * 32 + mt * 16;
            unsigned a[4];
            a[0] = XSu[(m0 + g) * XST + k0 + t];
            a[1] = XSu[(m0 + g + 8) * XST + k0 + t];
            a[2] = XSu[(m0 + g) * XST + k0 + t + 4];
            a[3] = XSu[(m0 + g + 8) * XST + k0 + t + 4];
#pragma unroll
            for (int nt = 0; nt < 8; nt++) mma_tf32(d[mt][nt], a, b[nt]);
        }
    }
}

// raw-float smem variant (cp.async path): convert after LDS
__device__ __forceinline__ void mma_block_raw(float d[2][8][4],
                                              const float* XS, const float* WS,
                                              int w, int g, int t)
{
#pragma unroll
    for (int kt = 0; kt < 8; kt++) {
        int k0 = kt * 8;
        unsigned b[8][2];
#pragma unroll
        for (int nt = 0; nt < 8; nt++) {
            b[nt][0] = f2tf32(WS[(k0 + t) * XST + nt * 8 + g]);
            b[nt][1] = f2tf32(WS[(k0 + t + 4) * XST + nt * 8 + g]);
        }
#pragma unroll
        for (int mt = 0; mt < 2; mt++) {
            int m0 = w * 32 + mt * 16;
            unsigned a[4];
            a[0] = f2tf32(XS[(m0 + g) * XST + k0 + t]);
            a[1] = f2tf32(XS[(m0 + g + 8) * XST + k0 + t]);
            a[2] = f2tf32(XS[(m0 + g) * XST + k0 + t + 4]);
            a[3] = f2tf32(XS[(m0 + g + 8) * XST + k0 + t + 4]);
#pragma unroll
            for (int nt = 0; nt < 8; nt++) mma_tf32(d[mt][nt], a, b[nt]);
        }
    }
}

// ---------------------------------------------------------------------------
// Unified GEMM kernel
//  MODE: 0 plain X, 1 cluster-mean-subtract, 2 concat [X | mix-on-the-fly]
//  EPI : 0 store raw, 1 bn_relu store, 2 bn_relu store + scatter(+cnt),
//        3 bn_relu * PW/(denom+1e-6) scatter only (no store)
// ---------------------------------------------------------------------------
template <int MODE, int EPI, int STATS, int MAXRED>
__global__ void __launch_bounds__(128) gemmk(GP p)
{
    extern __shared__ float sm[];
    unsigned* XSu = (unsigned*)sm;
    unsigned* WSu = (unsigned*)(sm + SM_XS);
    float* SC   = sm + SM_XS + SM_WS;
    float* SH   = SC + 64;
    float* SSUM = SH + 64;
    float* SSQ  = SSUM + 64;
    float* RED  = SSQ + 64;

    const int tid  = threadIdx.x;
    const int base = blockIdx.x * 128;
    const int lane = tid & 31, w = tid >> 5, g = lane >> 2, t = lane & 3;

    if (EPI >= 1 && tid < 64) { SC[tid] = p.bnc[tid]; SH[tid] = p.bnc[64 + tid]; }
    if (STATS && tid < 64)    { SSUM[tid] = 0.f; SSQ[tid] = 0.f; }

    float d[2][8][4];
#pragma unroll
    for (int mt = 0; mt < 2; mt++)
#pragma unroll
        for (int nt = 0; nt < 8; nt++)
#pragma unroll
            for (int i = 0; i < 4; i++) d[mt][nt][i] = 0.f;

    const int NP = (MODE == 2) ? 2 : 1;
    for (int pp = 0; pp < NP; pp++) {
        __syncthreads();
        load_w_tile(WSu, p.W + pp * 4096, tid);
        load_x_tile<MODE, EPI>(XSu, p, pp, base, tid);
        __syncthreads();
        mma_block(d, XSu, WSu, w, g, t);
    }
    __syncthreads();

    // ---- epilogue ----
#pragma unroll
    for (int mt = 0; mt < 2; mt++) {
        int r0 = base + w * 32 + mt * 16 + g;
        int r1 = r0 + 8;
        int cr0 = 0, cr1 = 0;
        if (EPI >= 2) {
            if (r0 < p.nrows) cr0 = p.cl[r0];
            if (r1 < p.nrows) cr1 = p.cl[r1];
        }
#pragma unroll
        for (int nt = 0; nt < 8; nt++) {
            int c0 = nt * 8 + 2 * t;
            float v0 = d[mt][nt][0], v1 = d[mt][nt][1];
            float v2 = d[mt][nt][2], v3 = d[mt][nt][3];
            if (EPI >= 1) {
                v0 = fmaxf(v0 * SC[c0] + SH[c0], 0.f);
                v1 = fmaxf(v1 * SC[c0 + 1] + SH[c0 + 1], 0.f);
                v2 = fmaxf(v2 * SC[c0] + SH[c0], 0.f);
                v3 = fmaxf(v3 * SC[c0 + 1] + SH[c0 + 1], 0.f);
            }
            if (EPI <= 2) {
                if (r0 < p.nrows)
                    *(float2*)(p.Y + (size_t)r0 * 64 + c0) = make_float2(v0, v1);
                if (r1 < p.nrows)
                    *(float2*)(p.Y + (size_t)r1 * 64 + c0) = make_float2(v2, v3);
            }
            if (EPI == 2) {
                if (r0 < p.nrows) {
                    atomicAdd(&p.scat[(size_t)cr0 * 64 + c0],     v0);
                    atomicAdd(&p.scat[(size_t)cr0 * 64 + c0 + 1], v1);
                }
                if (r1 < p.nrows) {
                    atomicAdd(&p.scat[(size_t)cr1 * 64 + c0],     v2);
                    atomicAdd(&p.scat[(size_t)cr1 * 64 + c0 + 1], v3);
                }
            }
            if (EPI == 3) {
                if (r0 < p.nrows) {
                    float2 pw = *(const float2*)(p.PW + (size_t)r0 * 64 + c0);
                    float2 dn = *(const float2*)(p.denom + (size_t)cr0 * 64 + c0);
                    atomicAdd(&p.scat[(size_t)cr0 * 64 + c0],     v0 * (pw.x / (dn.x + 1e-6f)));
                    atomicAdd(&p.scat[(size_t)cr0 * 64 + c0 + 1], v1 * (pw.y / (dn.y + 1e-6f)));
                }
                if (r1 < p.nrows) {
                    float2 pw = *(const float2*)(p.PW + (size_t)r1 * 64 + c0);
                    float2 dn = *(const float2*)(p.denom + (size_t)cr1 * 64 + c0);
                    atomicAdd(&p.scat[(size_t)cr1 * 64 + c0],     v2 * (pw.x / (dn.x + 1e-6f)));
                    atomicAdd(&p.scat[(size_t)cr1 * 64 + c0 + 1], v3 * (pw.y / (dn.y + 1e-6f)));
                }
            }
        }
    }

    if (STATS) {
#pragma unroll
        for (int nt = 0; nt < 8; nt++) {
            float s0 = 0.f, s1 = 0.f, q0 = 0.f, q1 = 0.f;
#pragma unroll
            for (int mt = 0; mt < 2; mt++) {
                int r0 = base + w * 32 + mt * 16 + g;
                if (r0 < p.nrows) {
                    s0 += d[mt][nt][0]; q0 += d[mt][nt][0] * d[mt][nt][0];
                    s1 += d[mt][nt][1]; q1 += d[mt][nt][1] * d[mt][nt][1];
                }
                if (r0 + 8 < p.nrows) {
                    s0 += d[mt][nt][2]; q0 += d[mt][nt][2] * d[mt][nt][2];
                    s1 += d[mt][nt][3]; q1 += d[mt][nt][3] * d[mt][nt][3];
                }
            }
            int c0 = nt * 8 + 2 * t;
            atomicAdd(&SSUM[c0], s0);     atomicAdd(&SSUM[c0 + 1], s1);
            atomicAdd(&SSQ[c0], q0);      atomicAdd(&SSQ[c0 + 1], q1);
        }
        __syncthreads();
        if (tid < 64) {
            atomicAdd(&g_stats[tid],      (double)SSUM[tid]);
            atomicAdd(&g_stats[64 + tid], (double)SSQ[tid]);
        }
    }
    if (MAXRED) {
        float m = -3.402823466e38f;
#pragma unroll
        for (int mt = 0; mt < 2; mt++) {
            int r0 = base + w * 32 + mt * 16 + g;
#pragma unroll
            for (int nt = 0; nt < 8; nt++) {
                if (r0 < p.nrows)     m = fmaxf(m, fmaxf(d[mt][nt][0], d[mt][nt][1]));
                if (r0 + 8 < p.nrows) m = fmaxf(m, fmaxf(d[mt][nt][2], d[mt][nt][3]));
            }
        }
#pragma unroll
        for (int o = 16; o > 0; o >>= 1)
            m = fmaxf(m, __shfl_xor_sync(0xffffffffu, m, o));
        if (lane == 0) RED[w] = m;
        __syncthreads();
        if (tid == 0) {
            m = fmaxf(fmaxf(RED[0], RED[1]), fmaxf(RED[2], RED[3]));
            atomicMaxFloat(&g_gmax, m);
        }
    }
}

// ---------------------------------------------------------------------------
// SYRK: S += X̃^T X̃ (tf32-rounded inputs, fp32 accum), m += colsum(X̃)
// ---------------------------------------------------------------------------
__global__ void __launch_bounds__(128) syrk_k(const float* __restrict__ X,
                                              float* __restrict__ S,
                                              float* __restrict__ M, int nrows)
{
    extern __shared__ float sm[];
    unsigned* XSu = (unsigned*)sm;
    const int tid  = threadIdx.x;
    const int base = blockIdx.x * 128;
    const int lane = tid & 31, w = tid >> 5, g = lane >> 2, t = lane & 3;

    // load tile (plain)
    int n = base + tid;
    if (n < nrows) {
        const float4* src = (const float4*)(X + (size_t)n * 64);
#pragma unroll
        for (int c4 = 0; c4 < 16; c4++) {
            float4 v = src[c4];
            uint4 u;
            u.x = f2tf32(v.x); u.y = f2tf32(v.y);
            u.z = f2tf32(v.z); u.w = f2tf32(v.w);
            *(uint4*)&XSu[tid * XST + c4 * 4] = u;
        }
    } else {
        uint4 z = make_uint4(0, 0, 0, 0);
#pragma unroll
        for (int c4 = 0; c4 < 16; c4++)
            *(uint4*)&XSu[tid * XST + c4 * 4] = z;
    }
    __syncthreads();

    const int m0 = w * 16;
    float d[8][4];
#pragma unroll
    for (int nt = 0; nt < 8; nt++)
#pragma unroll
        for (int i = 0; i < 4; i++) d[nt][i] = 0.f;

#pragma unroll
    for (int kt = 0; kt < 16; kt++) {
        int k0 = kt * 8;
        unsigned a[4];
        a[0] = XSu[(k0 + t) * XST + m0 + g];
        a[1] = XSu[(k0 + t) * XST + m0 + g + 8];
        a[2] = XSu[(k0 + t + 4) * XST + m0 + g];
        a[3] = XSu[(k0 + t + 4) * XST + m0 + g + 8];
#pragma unroll
        for (int nt = 0; nt < 8; nt++) {
            unsigned b[2];
            b[0] = XSu[(k0 + t) * XST + nt * 8 + g];
            b[1] = XSu[(k0 + t + 4) * XST + nt * 8 + g];
            mma_tf32(d[nt], a, b);
        }
    }
#pragma unroll
    for (int nt = 0; nt < 8; nt++) {
        int c0 = nt * 8 + 2 * t;
        atomicAdd(&S[(m0 + g) * 64 + c0],     d[nt][0]);
        atomicAdd(&S[(m0 + g) * 64 + c0 + 1], d[nt][1]);
        atomicAdd(&S[(m0 + g + 8) * 64 + c0],     d[nt][2]);
        atomicAdd(&S[(m0 + g + 8) * 64 + c0 + 1], d[nt][3]);
    }
    // column sums
    if (tid < 64) {
        float s = 0.f;
        for (int r = 0; r < 128; r++)
            s += __uint_as_float(XSu[r * XST + tid]);
        atomicAdd(&M[tid], s);
    }
}

// ---------------------------------------------------------------------------
// BN coefficients from (m, S, W, gamma, beta) for 7 slots
// ---------------------------------------------------------------------------
struct BC {
    const float* W[7];
    const float* gamma[7];
    const float* beta[7];
    float invN;
};

__global__ void bncoef_k(BC p, const float* __restrict__ S,
                         const float* __restrict__ M, float* __restrict__ bnc)
{
    __shared__ float Ss[4096];
    __shared__ float Ws[4096];
    __shared__ float ms[64];
    const int slot = blockIdx.x;
    const int j = threadIdx.x;  // 64 threads
    const float* W = p.W[slot];
    for (int i = j; i < 4096; i += 64) {
        Ss[i] = S[i];
        Ws[i] = __uint_as_float(f2tf32(W[i]));
    }
    ms[j] = M[j];
    __syncthreads();

    float mu = 0.f, ex2 = 0.f;
    for (int c = 0; c < 64; c++) {
        float wc = Ws[c * 64 + j];
        mu += ms[c] * wc;
        float inner = 0.f;
        for (int c2 = 0; c2 < 64; c2++)
            inner += Ss[c * 64 + c2] * Ws[c2 * 64 + j];
        ex2 += wc * inner;
    }
    mu *= p.invN; ex2 *= p.invN;
    float var = ex2 - mu * mu;
    float rs = rsqrtf(var + 1e-3f);
    float scale = p.gamma[slot][j] * rs;
    bnc[slot * 128 + j]      = scale;
    bnc[slot * 128 + 64 + j] = p.beta[slot][j] - mu * scale;
}

// finalize stats-based BN into slot 7
__global__ void finalize_k(const float* __restrict__ gamma,
                           const float* __restrict__ beta, float invN)
{
    int c = threadIdx.x;  // 64
    float mu  = (float)g_stats[c] * invN;
    float ex2 = (float)g_stats[64 + c] * invN;
    float var = ex2 - mu * mu;
    float rs  = rsqrtf(var + 1e-3f);
    float scale = gamma[c] * rs;
    g_bnc[7 * 128 + c]      = scale;
    g_bnc[7 * 128 + 64 + c] = beta[c] - mu * scale;
}

// ---------------------------------------------------------------------------
// Pipelined 27-tap conv (cp.async double buffer) + BN stats
// ---------------------------------------------------------------------------
__device__ __forceinline__ void cpa16(void* smem_dst, const void* gsrc, int sz) {
    unsigned d = (unsigned)__cvta_generic_to_shared(smem_dst);
    asm volatile("cp.async.cg.shared.global [%0], [%1], 16, %2;\n"
                 :: "r"(d), "l"(gsrc), "r"(sz));
}
__device__ __forceinline__ void cpa_commit() {
    asm volatile("cp.async.commit_group;\n");
}
template <int N>
__device__ __forceinline__ void cpa_wait() {
    asm volatile("cp.async.wait_group %0;\n" :: "n"(N));
}

__global__ void __launch_bounds__(128) conv27p(
    const float* __restrict__ F, const int* __restrict__ nbr,
    const float* __restrict__ Wc, float* __restrict__ Y, int nrows)
{
    extern __shared__ float sm[];
    float* XB0 = sm;
    float* XB1 = sm + CSM_X;
    float* WB0 = sm + 2 * CSM_X;
    float* WB1 = sm + 2 * CSM_X + CSM_W;
    float* SSUM = sm + 2 * CSM_X + 2 * CSM_W;
    float* SSQ  = SSUM + 64;

    const int tid  = threadIdx.x;
    const int base = blockIdx.x * 128;
    const int lane = tid & 31, w = tid >> 5, g = lane >> 2, t = lane & 3;
    const int n = base + tid;
    const int wr = tid >> 1, wh = (tid & 1) * 32;

    if (tid < 64) { SSUM[tid] = 0.f; SSQ[tid] = 0.f; }

    float d[2][8][4];
#pragma unroll
    for (int mt = 0; mt < 2; mt++)
#pragma unroll
        for (int nt = 0; nt < 8; nt++)
#pragma unroll
            for (int i = 0; i < 4; i++) d[mt][nt][i] = 0.f;

    auto prefetch = [&](int k, float* XB, float* WB) {
        const float* src = F;
        int sz = 0;
        if (n < nrows) {
            int idx = __ldg(&nbr[(size_t)n * KTAP + k]);
            src = F + (size_t)idx * 64;
            sz = 16;
        }
#pragma unroll
        for (int c4 = 0; c4 < 16; c4++)
            cpa16(XB + tid * XST + c4 * 4, src + c4 * 4, sz);
        const float* ws = Wc + k * 4096 + wr * 64 + wh;
#pragma unroll
        for (int c4 = 0; c4 < 8; c4++)
            cpa16(WB + wr * XST + wh + c4 * 4, ws + c4 * 4, 16);
    };

    prefetch(0, XB0, WB0);
    cpa_commit();

    for (int k = 0; k < KTAP; k++) {
        float* XB = (k & 1) ? XB1 : XB0;
        float* WB = (k & 1) ? WB1 : WB0;
        if (k + 1 < KTAP) {
            prefetch(k + 1, (k & 1) ? XB0 : XB1, (k & 1) ? WB0 : WB1);
            cpa_commit();
            cpa_wait<1>();
        } else {
            cpa_wait<0>();
        }
        __syncthreads();
        mma_block_raw(d, XB, WB, w, g, t);
        __syncthreads();
    }

    // store + stats
#pragma unroll
    for (int mt = 0; mt < 2; mt++) {
        int r0 = base + w * 32 + mt * 16 + g;
        int r1 = r0 + 8;
#pragma unroll
        for (int nt = 0; nt < 8; nt++) {
            int c0 = nt * 8 + 2 * t;
            if (r0 < nrows)
                *(float2*)(Y + (size_t)r0 * 64 + c0) = make_float2(d[mt][nt][0], d[mt][nt][1]);
            if (r1 < nrows)
                *(float2*)(Y + (size_t)r1 * 64 + c0) = make_float2(d[mt][nt][2], d[mt][nt][3]);
        }
    }
#pragma unroll
    for (int nt = 0; nt < 8; nt++) {
        float s0 = 0.f, s1 = 0.f, q0 = 0.f, q1 = 0.f;
#pragma unroll
        for (int mt = 0; mt < 2; mt++) {
            int r0 = base + w * 32 + mt * 16 + g;
            if (r0 < nrows) {
                s0 += d[mt][nt][0]; q0 += d[mt][nt][0] * d[mt][nt][0];
                s1 += d[mt][nt][1]; q1 += d[mt][nt][1] * d[mt][nt][1];
            }
            if (r0 + 8 < nrows) {
                s0 += d[mt][nt][2]; q0 += d[mt][nt][2] * d[mt][nt][2];
                s1 += d[mt][nt][3]; q1 += d[mt][nt][3] * d[mt][nt][3];
            }
        }
        int c0 = nt * 8 + 2 * t;
        atomicAdd(&SSUM[c0], s0);     atomicAdd(&SSUM[c0 + 1], s1);
        atomicAdd(&SSQ[c0], q0);      atomicAdd(&SSQ[c0 + 1], q1);
    }
    __syncthreads();
    if (tid < 64) {
        atomicAdd(&g_stats[tid],      (double)SSUM[tid]);
        atomicAdd(&g_stats[64 + tid], (double)SSQ[tid]);
    }
}

// ---------------------------------------------------------------------------
// Elementwise kernels (float4)
// ---------------------------------------------------------------------------
__global__ void zero4(float4* a, int na, float4* b, int nb,
                      float4* c, int nc, int flags)
{
    int i = blockIdx.x * blockDim.x + threadIdx.x;
    float4 z = make_float4(0.f, 0.f, 0.f, 0.f);
    if (a && i < na) a[i] = z;
    if (b && i < nb) b[i] = z;
    if (c && i < nc) c[i] = z;
    if ((flags & 1) && i < 128) g_stats[i] = 0.0;
    if ((flags & 2) && i == 0)  g_gmax = -3.402823466e38f;
    if (flags & 4) {
        if (i < 1024) ((float4*)g_S)[i] = z;
        if (i < 16)   ((float4*)g_m)[i] = z;
    }
}

__global__ void adp_kernel(const float* __restrict__ feat,
                           const float* __restrict__ Wadp,
                           float* __restrict__ adp, int n)
{
    __shared__ float w[192];
    int tid = threadIdx.x;
    if (tid < 192) w[tid] = Wadp[tid];
    __syncthreads();
    int r = blockIdx.x * blockDim.x + tid;
    if (r >= n) return;
    const float4* f = (const float4*)(feat + (size_t)r * 64);
    float l0 = 0.f, l1 = 0.f, l2 = 0.f;
#pragma unroll
    for (int c4 = 0; c4 < 16; c4++) {
        float4 v = f[c4];
        int c = c4 * 4;
        l0 += v.x * w[(c + 0) * 3 + 0] + v.y * w[(c + 1) * 3 + 0] +
              v.z * w[(c + 2) * 3 + 0] + v.w * w[(c + 3) * 3 + 0];
        l1 += v.x * w[(c + 0) * 3 + 1] + v.y * w[(c + 1) * 3 + 1] +
              v.z * w[(c + 2) * 3 + 1] + v.w * w[(c + 3) * 3 + 1];
        l2 += v.x * w[(c + 0) * 3 + 2] + v.y * w[(c + 1) * 3 + 2] +
              v.z * w[(c + 2) * 3 + 2] + v.w * w[(c + 3) * 3 + 2];
    }
    float m = fmaxf(l0, fmaxf(l1, l2));
    float e0 = expf(l0 - m), e1 = expf(l1 - m), e2 = expf(l2 - m);
    float inv = 1.f / (e0 + e1 + e2);
    adp[(size_t)r * 3 + 0] = e0 * inv;
    adp[(size_t)r * 3 + 1] = e1 * inv;
    adp[(size_t)r * 3 + 2] = e2 * inv;
}

__global__ void exp_scatter_f4(const float4* __restrict__ X,
                               float4* __restrict__ out,
                               const int* __restrict__ cl,
                               float* __restrict__ B, int n)
{
    int i = blockIdx.x * blockDim.x + threadIdx.x;
    if (i >= n * 16) return;
    int r = i >> 4, c = (i & 15) * 4;
    float gm = g_gmax;
    float4 x = X[i];
    float4 e;
    e.x = expf(x.x - gm); e.y = expf(x.y - gm);
    e.z = expf(x.z - gm); e.w = expf(x.w - gm);
    out[i] = e;
    size_t co = (size_t)cl[r] * 64 + c;
    atomicAdd(&B[co],     e.x);
    atomicAdd(&B[co + 1], e.y);
    atomicAdd(&B[co + 2], e.z);
    atomicAdd(&B[co + 3], e.w);
}

// OP 0: out = relu(y)          (y = x*sc + sh, slot 7)
// OP 1: out = relu(y) + add
// OP 2: out = relu(y + add)
template <int OP>
__global__ void bnapply_f4(const float4* __restrict__ X,
                           const float4* __restrict__ add,
                           float4* __restrict__ out, int n)
{
    __shared__ float SC[64], SH[64];
    int tid = threadIdx.x;
    if (tid < 64) { SC[tid] = g_bnc[7 * 128 + tid]; SH[tid] = g_bnc[7 * 128 + 64 + tid]; }
    __syncthreads();
    int i = blockIdx.x * blockDim.x + tid;
    if (i >= n * 16) return;
    int c = (i & 15) * 4;
    float4 x = X[i];
    float4 y;
    y.x = x.x * SC[c]     + SH[c];
    y.y = x.y * SC[c + 1] + SH[c + 1];
    y.z = x.z * SC[c + 2] + SH[c + 2];
    y.w = x.w * SC[c + 3] + SH[c + 3];
    float4 o;
    if (OP == 0) {
        o.x = fmaxf(y.x, 0.f); o.y = fmaxf(y.y, 0.f);
        o.z = fmaxf(y.z, 0.f); o.w = fmaxf(y.w, 0.f);
    } else if (OP == 1) {
        float4 a = add[i];
        o.x = fmaxf(y.x, 0.f) + a.x; o.y = fmaxf(y.y, 0.f) + a.y;
        o.z = fmaxf(y.z, 0.f) + a.z; o.w = fmaxf(y.w, 0.f) + a.w;
    } else {
        float4 a = add[i];
        o.x = fmaxf(y.x + a.x, 0.f); o.y = fmaxf(y.y + a.y, 0.f);
        o.z = fmaxf(y.z + a.z, 0.f); o.w = fmaxf(y.w + a.w, 0.f);
    }
    out[i] = o;
}

// ---------------------------------------------------------------------------
// Host launcher
// ---------------------------------------------------------------------------
extern "C" void kernel_launch(void* const* d_in, const int* in_sizes, int n_in,
                              void* d_out, int out_size)
{
    const float* feat   = (const float*)d_in[0];
    const int*   cl[3]  = {(const int*)d_in[1], (const int*)d_in[2], (const int*)d_in[3]};
    const int*   nbr    = (const int*)d_in[4];
    const float* W_lw   = (const float*)d_in[5];
    const float* g_lw   = (const float*)d_in[6];
    const float* b_lw   = (const float*)d_in[7];
    const float* W_w    = (const float*)d_in[8];
    const float* W_proj = (const float*)d_in[9];
    const float* g_proj = (const float*)d_in[10];
    const float* b_proj = (const float*)d_in[11];
    const float* W_adp  = (const float*)d_in[12];
    const float* W_fuse = (const float*)d_in[13];
    const float* g_fuse = (const float*)d_in[14];
    const float* b_fuse = (const float*)d_in[15];
    const float* W_c1   = (const float*)d_in[16];
    const float* g_c1   = (const float*)d_in[17];
    const float* b_c1   = (const float*)d_in[18];
    const float* W_c2   = (const float*)d_in[19];
    const float* g_c2   = (const float*)d_in[20];
    const float* b_c2   = (const float*)d_in[21];

    const int   n    = in_sizes[0] / 64;
    const float invN = 1.f / (float)n;
    float* out = (float*)d_out;

    float *bx, *bp, *bf, *sumb, *den, *pf[3], *cc, *adpb, *Sg, *Mg, *bnc;
    cudaGetSymbolAddress((void**)&bx,    g_bufX);
    cudaGetSymbolAddress((void**)&bp,    g_bufP);
    cudaGetSymbolAddress((void**)&bf,    g_bufF);
    cudaGetSymbolAddress((void**)&sumb,  g_sum);
    cudaGetSymbolAddress((void**)&den,   g_den);
    cudaGetSymbolAddress((void**)&pf[0], g_pf0);
    cudaGetSymbolAddress((void**)&pf[1], g_pf1);
    cudaGetSymbolAddress((void**)&pf[2], g_pf2);
    cudaGetSymbolAddress((void**)&cc,    g_ccnt);
    cudaGetSymbolAddress((void**)&adpb,  g_adpw);
    cudaGetSymbolAddress((void**)&Sg,    g_S);
    cudaGetSymbolAddress((void**)&Mg,    g_m);
    cudaGetSymbolAddress((void**)&bnc,   g_bnc);

    cudaFuncSetAttribute(gemmk<0,2,0,0>, cudaFuncAttributeMaxDynamicSharedMemorySize, GEMM_SM_BYTES);
    cudaFuncSetAttribute(gemmk<1,0,0,1>, cudaFuncAttributeMaxDynamicSharedMemorySize, GEMM_SM_BYTES);
    cudaFuncSetAttribute(gemmk<0,3,0,0>, cudaFuncAttributeMaxDynamicSharedMemorySize, GEMM_SM_BYTES);
    cudaFuncSetAttribute(gemmk<0,1,0,0>, cudaFuncAttributeMaxDynamicSharedMemorySize, GEMM_SM_BYTES);
    cudaFuncSetAttribute(gemmk<2,0,1,0>, cudaFuncAttributeMaxDynamicSharedMemorySize, GEMM_SM_BYTES);
    cudaFuncSetAttribute(syrk_k,  cudaFuncAttributeMaxDynamicSharedMemorySize, (SM_XS + 64) * 4);
    cudaFuncSetAttribute(conv27p, cudaFuncAttributeMaxDynamicSharedMemorySize, CONV_SM_BYTES);

    const int GB = (n + 127) / 128;
    const int E4 = (n * 16 + 255) / 256;

    GP base{};
    base.nrows = n;

    // 1. zero pf buffers + S + m
    {
        int mx = 131072 * 16;  // pf2 float4 count
        zero4<<<(mx + 255) / 256, 256>>>((float4*)pf[0], 4096 * 16,
                                         (float4*)pf[1], 32768 * 16,
                                         (float4*)pf[2], 131072 * 16, 4);
    }
    // 2. adaptive weights
    adp_kernel<<<(n + 255) / 256, 256>>>(feat, W_adp, adpb, n);
    // 3. SYRK over feat
    syrk_k<<<GB, 128, (SM_XS + 64) * 4>>>(feat, Sg, Mg, n);
    // 4. BN coefficients for the 7 feat-side GEMMs
    {
        BC bc{};
        for (int i = 0; i < 3; i++) {
            bc.W[i] = W_lw + i * 4096;   bc.gamma[i] = g_lw + i * 64;   bc.beta[i] = b_lw + i * 64;
            bc.W[3 + i] = W_proj + i * 4096; bc.gamma[3 + i] = g_proj + i * 64; bc.beta[3 + i] = b_proj + i * 64;
        }
        bc.W[6] = W_proj + 3 * 4096; bc.gamma[6] = g_proj + 192; bc.beta[6] = b_proj + 192;
        bc.invN = invN;
        bncoef_k<<<7, 64>>>(bc, Sg, Mg, bnc);
    }

    // ---- three branches ----
    for (int i = 0; i < 3; i++) {
        const int nci = NCL_H[i];
        zero4<<<(nci * 16 + 255) / 256, 256>>>((float4*)sumb, nci * 16,
                                               (float4*)cc, nci / 4,
                                               (float4*)den, nci * 16, 2);
        // pw = relu(bn(feat @ W_lw[i])) -> bp; scatter sums + counts
        {
            GP p = base;
            p.X = feat; p.W = W_lw + i * 4096; p.Y = bp;
            p.cl = cl[i]; p.scat = sumb; p.cnt = cc;
            p.bnc = bnc + i * 128;
            gemmk<0,2,0,0><<<GB, 128, GEMM_SM_BYTES>>>(p);
        }
        // t = (pw - mean[cl]) @ W_w[i] -> bx ; global max
        {
            GP p = base;
            p.X = bp; p.W = W_w + i * 4096; p.Y = bx;
            p.cl = cl[i]; p.csum = sumb; p.ccnt = cc;
            gemmk<1,0,0,1><<<GB, 128, GEMM_SM_BYTES>>>(p);
        }
        // pw2 = exp(t - gmax) -> bp ; scatter denom
        exp_scatter_f4<<<E4, 256>>>((const float4*)bx, (float4*)bp, cl[i], den, n);
        // pf_i[cl] += relu(bn(feat @ W_proj[i])) * pw2/(denom+1e-6)
        {
            GP p = base;
            p.X = feat; p.W = W_proj + i * 4096;
            p.cl = cl[i]; p.scat = pf[i];
            p.PW = bp; p.denom = den;
            p.bnc = bnc + (3 + i) * 128;
            gemmk<0,3,0,0><<<GB, 128, GEMM_SM_BYTES>>>(p);
        }
    }

    // f_last = relu(bn(feat @ W_proj[3])) -> bp
    {
        GP p = base;
        p.X = feat; p.W = W_proj + 3 * 4096; p.Y = bp;
        p.bnc = bnc + 6 * 128;
        gemmk<0,1,0,0><<<GB, 128, GEMM_SM_BYTES>>>(p);
    }

    // fuse: [f_last | mix] @ W_fuse -> bx (+stats); mix built on the fly
    zero4<<<1, 256>>>(nullptr, 0, nullptr, 0, nullptr, 0, 1);
    {
        GP p = base;
        p.X = bp; p.W = W_fuse; p.Y = bx;
        p.adp = adpb;
        p.cl0 = cl[0]; p.cl1 = cl[1]; p.cl2 = cl[2];
        p.pf0 = pf[0]; p.pf1 = pf[1]; p.pf2 = pf[2];
        gemmk<2,0,1,0><<<GB, 128, GEMM_SM_BYTES>>>(p);
    }
    finalize_k<<<1, 64>>>(g_fuse, b_fuse, invN);
    bnapply_f4<1><<<E4, 256>>>((const float4*)bx, (const float4*)feat, (float4*)bf, n);

    // conv1 -> bn -> relu  (h1 -> bp)
    zero4<<<1, 256>>>(nullptr, 0, nullptr, 0, nullptr, 0, 1);
    conv27p<<<GB, 128, CONV_SM_BYTES>>>(bf, nbr, W_c1, bx, n);
    finalize_k<<<1, 64>>>(g_c1, b_c1, invN);
    bnapply_f4<0><<<E4, 256>>>((const float4*)bx, nullptr, (float4*)bp, n);

    // conv2 -> bn ; out = relu(h + fused)
    zero4<<<1, 256>>>(nullptr, 0, nullptr, 0, nullptr, 0, 1);
    conv27p<<<GB, 128, CONV_SM_BYTES>>>(bp, nbr, W_c2, bx, n);
    finalize_k<<<1, 64>>>(g_c2, b_c2, invN);
    bnapply_f4<2><<<E4, 256>>>((const float4*)bx, (const float4*)bf, (float4*)out, n);
}